// round 2
// baseline (speedup 1.0000x reference)
#include <cuda_runtime.h>
#include <cooperative_groups.h>

namespace cg = cooperative_groups;

#define TT 1200
#define BB 256
#define HH 128
#define II 16
#define CSIZE 4
#define BC 8          // batch per cluster
#define NTHREADS 256
#define NCTAS 128     // 32 clusters * 4

// Dynamic shared layout: all weights resident for the whole run.
struct Smem {
    float Wih0[II][HH];    // [k][lr], lr = jj*4 + gate
    float Whh0[HH][HH];
    float Wih1[HH][HH];
    float Whh1[HH][HH];
    float b0[HH];          // b_ih0 + b_hh0, permuted to lr
    float b1[HH];
    float wlin[HH];        // plain h-index order
    float h0buf[2][HH][BC];  // [buf][h_index][b], full h replicated per CTA
    float h1buf[2][HH][BC];
    float xs[II][BC];
    float red[32][36];     // cross-warp-half partial sums, padded rows
    float blin;
};

__device__ __forceinline__ float sig_f(float x) {
    return __fdividef(1.0f, 1.0f + __expf(-x));
}
__device__ __forceinline__ float tanh_f(float x) {
    return __fdividef(2.0f, 1.0f + __expf(-2.0f * x)) - 1.0f;
}

// Accumulate acc[g][b] += W[k][lroff+g] * src[k][b] over this thread's k-slice.
template <int KT>
__device__ __forceinline__ void accum(float acc[4][8],
                                      const float* __restrict__ W,
                                      const float* __restrict__ src,
                                      int ks, int lroff) {
    constexpr int KPT = KT / 8;
    const float* Wp = W + ks * KPT * HH + lroff;
    const float* Sp = src + ks * KPT * BC;
#pragma unroll
    for (int k = 0; k < KPT; k++) {
        float4 wv = *(const float4*)(Wp + k * HH);
        float4 s0 = *(const float4*)(Sp + k * BC);
        float4 s1 = *(const float4*)(Sp + k * BC + 4);
        float s[8] = {s0.x, s0.y, s0.z, s0.w, s1.x, s1.y, s1.z, s1.w};
#pragma unroll
        for (int b = 0; b < 8; b++) {
            acc[0][b] = fmaf(wv.x, s[b], acc[0][b]);
            acc[1][b] = fmaf(wv.y, s[b], acc[1][b]);
            acc[2][b] = fmaf(wv.z, s[b], acc[2][b]);
            acc[3][b] = fmaf(wv.w, s[b], acc[3][b]);
        }
    }
}

// Butterfly-reduce the 4 in-warp k-slices, combine warp halves through smem,
// apply gates, update c, and push h to all 4 cluster CTAs via DSMEM.
__device__ __forceinline__ void reduce_update_store(
    float acc[4][8], float* __restrict__ red, const float* __restrict__ bias,
    float cpair[2], float (*hdst)[BC], int q, int warp, int lane,
    cg::cluster_group& cluster) {
#pragma unroll
    for (int g = 0; g < 4; g++)
#pragma unroll
        for (int b = 0; b < 8; b++) {
            acc[g][b] += __shfl_xor_sync(0xffffffffu, acc[g][b], 8);
            acc[g][b] += __shfl_xor_sync(0xffffffffu, acc[g][b], 16);
        }
    int jj = (warp & 3) * 8 + (lane & 7);
    if (warp >= 4 && lane < 8) {
        float* r = red + jj * 36;
#pragma unroll
        for (int g = 0; g < 4; g++) {
            *(float4*)(r + g * 8)     = make_float4(acc[g][0], acc[g][1], acc[g][2], acc[g][3]);
            *(float4*)(r + g * 8 + 4) = make_float4(acc[g][4], acc[g][5], acc[g][6], acc[g][7]);
        }
    }
    __syncthreads();
    if (warp < 4) {
        const float* r = red + jj * 36;
        int bp = (lane >> 3) * 2;
        float hv[2];
#pragma unroll
        for (int u = 0; u < 2; u++) {
            int b = bp + u;
            float iv = sig_f (acc[0][b] + r[0 * 8 + b] + bias[jj * 4 + 0]);
            float fv = sig_f (acc[1][b] + r[1 * 8 + b] + bias[jj * 4 + 1]);
            float gv = tanh_f(acc[2][b] + r[2 * 8 + b] + bias[jj * 4 + 2]);
            float ov = sig_f (acc[3][b] + r[3 * 8 + b] + bias[jj * 4 + 3]);
            float c = fv * cpair[u] + iv * gv;
            cpair[u] = c;
            hv[u] = ov * tanh_f(c);
        }
        float2 h2 = make_float2(hv[0], hv[1]);
        float* lp = &hdst[q * 32 + jj][bp];
#pragma unroll
        for (int r2 = 0; r2 < CSIZE; r2++) {
            float* dst = cluster.map_shared_rank(lp, r2);
            *(float2*)dst = h2;
        }
    }
}

__global__ void __cluster_dims__(CSIZE, 1, 1) __launch_bounds__(NTHREADS, 1)
lstm_kernel(const float* __restrict__ x,
            const float* __restrict__ Wih0, const float* __restrict__ Whh0,
            const float* __restrict__ bih0, const float* __restrict__ bhh0,
            const float* __restrict__ Wih1, const float* __restrict__ Whh1,
            const float* __restrict__ bih1, const float* __restrict__ bhh1,
            const float* __restrict__ Wlin, const float* __restrict__ blin,
            float* __restrict__ out) {
    extern __shared__ char smem_bytes[];
    Smem* sm = (Smem*)smem_bytes;
    cg::cluster_group cluster = cg::this_cluster();
    const int q = cluster.block_rank();           // 0..3 -> h-indices [q*32, q*32+32)
    const int tid = threadIdx.x;
    const int warp = tid >> 5, lane = tid & 31;
    const int cid = blockIdx.x / CSIZE;
    const int bbase = cid * BC;

    // ---- Load this CTA's weight slice (one-time, L2-served) ----
    for (int idx = tid; idx < HH * HH; idx += NTHREADS) {
        int k = idx >> 7, lr = idx & 127;
        int g = lr & 3, jj = lr >> 2;
        int grow = g * HH + q * 32 + jj;          // global gate row in [0,512)
        sm->Whh0[k][lr] = Whh0[grow * HH + k];
        sm->Wih1[k][lr] = Wih1[grow * HH + k];
        sm->Whh1[k][lr] = Whh1[grow * HH + k];
        if (k < II) sm->Wih0[k][lr] = Wih0[grow * II + k];
    }
    for (int lr = tid; lr < HH; lr += NTHREADS) {
        int g = lr & 3, jj = lr >> 2;
        int grow = g * HH + q * 32 + jj;
        sm->b0[lr] = bih0[grow] + bhh0[grow];
        sm->b1[lr] = bih1[grow] + bhh1[grow];
        sm->wlin[lr] = Wlin[lr];                  // plain index, no permutation
    }
    if (tid == 0) sm->blin = blin[0];
    for (int i = tid; i < 2 * HH * BC; i += NTHREADS) {
        ((float*)sm->h0buf)[i] = 0.0f;
        ((float*)sm->h1buf)[i] = 0.0f;
    }
    __syncthreads();
    cluster.sync();   // peers may write our h buffers from step 0 on

    float c0[2] = {0.0f, 0.0f}, c1[2] = {0.0f, 0.0f};
    const int lroff = ((warp & 3) * 8 + (lane & 7)) * 4;   // 4 contiguous lr rows
    const int ks = (warp >> 2) * 4 + (lane >> 3);          // k-slice 0..7

    for (int t = 0; t < TT; t++) {
        const int cur = t & 1, nxt = cur ^ 1;

        // stage x[:, t, :] for our batch slice
        if (tid < II * BC) {
            int b = tid >> 4, k = tid & 15;
            sm->xs[k][b] = x[((size_t)(bbase + b) * TT + t) * II + k];
        }
        __syncthreads();

        // ---- Layer 0 ----
        float acc[4][8];
#pragma unroll
        for (int g = 0; g < 4; g++)
#pragma unroll
            for (int b = 0; b < 8; b++) acc[g][b] = 0.0f;
        accum<II>(acc, &sm->Wih0[0][0], &sm->xs[0][0], ks, lroff);
        accum<HH>(acc, &sm->Whh0[0][0], &sm->h0buf[cur][0][0], ks, lroff);
        reduce_update_store(acc, &sm->red[0][0], sm->b0, c0, sm->h0buf[nxt],
                            q, warp, lane, cluster);
        cluster.sync();

        // ---- Layer 1 (consumes layer-0 h of the same step) ----
#pragma unroll
        for (int g = 0; g < 4; g++)
#pragma unroll
            for (int b = 0; b < 8; b++) acc[g][b] = 0.0f;
        accum<HH>(acc, &sm->Wih1[0][0], &sm->h0buf[nxt][0][0], ks, lroff);
        accum<HH>(acc, &sm->Whh1[0][0], &sm->h1buf[cur][0][0], ks, lroff);
        reduce_update_store(acc, &sm->red[0][0], sm->b1, c1, sm->h1buf[nxt],
                            q, warp, lane, cluster);
        cluster.sync();

        // ---- Fused ReLU + linear head (warp 7; others run ahead to t+1) ----
        if (warp == 7) {
            int b = lane & 7, kq = lane >> 3;
            float p = 0.0f;
#pragma unroll
            for (int i = 0; i < 32; i++) {
                int k = kq * 32 + i;
                float h = fmaxf(sm->h1buf[nxt][k][b], 0.0f);
                p = fmaf(h, sm->wlin[k], p);
            }
            p += __shfl_xor_sync(0xffffffffu, p, 8);
            p += __shfl_xor_sync(0xffffffffu, p, 16);
            if (lane < 8)
                out[(size_t)(bbase + b) * TT + t] = p + sm->blin;
        }
    }
}

extern "C" void kernel_launch(void* const* d_in, const int* in_sizes, int n_in,
                              void* d_out, int out_size) {
    const float* x    = (const float*)d_in[0];
    const float* Wih0 = (const float*)d_in[1];
    const float* Whh0 = (const float*)d_in[2];
    const float* bih0 = (const float*)d_in[3];
    const float* bhh0 = (const float*)d_in[4];
    const float* Wih1 = (const float*)d_in[5];
    const float* Whh1 = (const float*)d_in[6];
    const float* bih1 = (const float*)d_in[7];
    const float* bhh1 = (const float*)d_in[8];
    const float* Wlin = (const float*)d_in[9];
    const float* blin = (const float*)d_in[10];
    float* out = (float*)d_out;

    size_t smem = sizeof(Smem);
    cudaFuncSetAttribute(lstm_kernel, cudaFuncAttributeMaxDynamicSharedMemorySize,
                         (int)smem);
    lstm_kernel<<<NCTAS, NTHREADS, smem>>>(x, Wih0, Whh0, bih0, bhh0,
                                           Wih1, Whh1, bih1, bhh1,
                                           Wlin, blin, out);
}

// round 3
// speedup vs baseline: 1.0857x; 1.0857x over previous
#include <cuda_runtime.h>
#include <cooperative_groups.h>
namespace cg = cooperative_groups;
typedef unsigned long long ull;

#define TT 1200
#define HH 128
#define II 16
#define CSIZE 4
#define BC 8
#define NT 256
#define NCTAS 128

struct __align__(16) Smem {
    float Wih0[II * HH];     // [k][lr], lr = jj*4+g
    float Whh0[HH * HH];
    float Wih1[HH * HH];
    float Whh1[HH * HH];
    float b0[HH], b1[HH], wlin[HH];
    float h0buf[2][HH * BC]; // [par][k*BC+b], full h replicated per CTA
    float h1buf[2][HH * BC];
    float xs[2][II * BC];
    float red[32][36];
    float blin;
};

#define CLUSTER_ARRIVE() asm volatile("barrier.cluster.arrive.aligned;" ::: "memory")
#define CLUSTER_WAIT()   asm volatile("barrier.cluster.wait.aligned;" ::: "memory")

__device__ __forceinline__ float sig_f(float x) {
    return __fdividef(1.0f, 1.0f + __expf(-x));
}
__device__ __forceinline__ float tanh_f(float x) {
    return __fdividef(2.0f, 1.0f + __expf(-2.0f * x)) - 1.0f;
}
__device__ __forceinline__ ull bcast2(float f) {
    ull r; asm("mov.b64 %0, {%1, %1};" : "=l"(r) : "f"(f)); return r;
}
__device__ __forceinline__ void fma2(ull& a, ull b, ull c) {
    asm("fma.rn.f32x2 %0, %1, %2, %0;" : "+l"(a) : "l"(b), "l"(c));
}
__device__ __forceinline__ ull add2(ull a, ull b) {
    ull r; asm("add.rn.f32x2 %0, %1, %2;" : "=l"(r) : "l"(a), "l"(b)); return r;
}
__device__ __forceinline__ void unpack2(ull v, float& lo, float& hi) {
    asm("mov.b64 {%0, %1}, %2;" : "=f"(lo), "=f"(hi) : "l"(v));
}

// acc[g][p] += W[k][lroff+g] * src[k][2p..2p+1] over this thread's k-slice.
template <int KP>
__device__ __forceinline__ void accum2(ull acc[4][4], const float* __restrict__ W,
                                       const float* __restrict__ S, int ks, int lroff) {
    const float* Wp = W + ks * KP * HH + lroff;
    const float* Sp = S + ks * KP * BC;
#pragma unroll
    for (int k = 0; k < KP; k++) {
        float4 wv = *(const float4*)(Wp + k * HH);
        ulonglong2 sa = *(const ulonglong2*)(Sp + k * BC);
        ulonglong2 sb = *(const ulonglong2*)(Sp + k * BC + 4);
        ull w[4] = {bcast2(wv.x), bcast2(wv.y), bcast2(wv.z), bcast2(wv.w)};
        ull s[4] = {sa.x, sa.y, sb.x, sb.y};
#pragma unroll
        for (int g = 0; g < 4; g++) {
            fma2(acc[g][0], w[g], s[0]); fma2(acc[g][1], w[g], s[1]);
            fma2(acc[g][2], w[g], s[2]); fma2(acc[g][3], w[g], s[3]);
        }
    }
}

// In-warp xor-8/16 reduce (packed), cross-half combine via smem, gates, c update,
// DSMEM-replicated h store into hdst[par].
__device__ __forceinline__ void rus(ull acc[4][4], Smem* sm, const float* __restrict__ bias,
                                    float cpair[2], float (*hdst)[HH * BC], int par,
                                    int q, int warp, int lane, cg::cluster_group& cl) {
#pragma unroll
    for (int g = 0; g < 4; g++)
#pragma unroll
        for (int p = 0; p < 4; p++) {
            acc[g][p] = add2(acc[g][p], __shfl_xor_sync(0xffffffffu, acc[g][p], 8));
            acc[g][p] = add2(acc[g][p], __shfl_xor_sync(0xffffffffu, acc[g][p], 16));
        }
    const int jj = (warp & 3) * 8 + (lane & 7);
    if (warp >= 4 && lane < 8) {
        ull* r = (ull*)&sm->red[jj][0];
#pragma unroll
        for (int g = 0; g < 4; g++) {
            r[g * 4 + 0] = acc[g][0]; r[g * 4 + 1] = acc[g][1];
            r[g * 4 + 2] = acc[g][2]; r[g * 4 + 3] = acc[g][3];
        }
    }
    __syncthreads();
    if (warp < 4) {
        const float* r = &sm->red[jj][0];
        const int pi = lane >> 3;          // packed pair: b = 2*pi, 2*pi+1
        float ga[4][2];
#pragma unroll
        for (int g = 0; g < 4; g++) {
            float lo, hi; unpack2(acc[g][pi], lo, hi);
            float bb = bias[jj * 4 + g];
            ga[g][0] = lo + r[g * 8 + 2 * pi]     + bb;
            ga[g][1] = hi + r[g * 8 + 2 * pi + 1] + bb;
        }
        float hv[2];
#pragma unroll
        for (int u = 0; u < 2; u++) {
            float iv = sig_f(ga[0][u]), fv = sig_f(ga[1][u]);
            float gv = tanh_f(ga[2][u]), ov = sig_f(ga[3][u]);
            float c = fv * cpair[u] + iv * gv;
            cpair[u] = c;
            hv[u] = ov * tanh_f(c);
        }
        float2 h2 = make_float2(hv[0], hv[1]);
        float* lp = &hdst[par][(q * 32 + jj) * BC + pi * 2];
#pragma unroll
        for (int r2 = 0; r2 < CSIZE; r2++)
            *(float2*)cl.map_shared_rank(lp, r2) = h2;
    }
}

__global__ void __cluster_dims__(CSIZE, 1, 1) __launch_bounds__(NT, 1)
lstm_kernel(const float* __restrict__ x,
            const float* __restrict__ Wih0, const float* __restrict__ Whh0,
            const float* __restrict__ bih0, const float* __restrict__ bhh0,
            const float* __restrict__ Wih1, const float* __restrict__ Whh1,
            const float* __restrict__ bih1, const float* __restrict__ bhh1,
            const float* __restrict__ Wlin, const float* __restrict__ blin,
            float* __restrict__ out) {
    extern __shared__ char smem_bytes[];
    Smem* sm = (Smem*)smem_bytes;
    cg::cluster_group cl = cg::this_cluster();
    const int q = cl.block_rank();
    const int tid = threadIdx.x, warp = tid >> 5, lane = tid & 31;
    const int bbase = (blockIdx.x / CSIZE) * BC;

    // ---- one-time weight load ----
    for (int idx = tid; idx < HH * HH; idx += NT) {
        int k = idx >> 7, lr = idx & 127;
        int g = lr & 3, jj = lr >> 2;
        int grow = g * HH + q * 32 + jj;
        sm->Whh0[k * HH + lr] = Whh0[grow * HH + k];
        sm->Wih1[k * HH + lr] = Wih1[grow * HH + k];
        sm->Whh1[k * HH + lr] = Whh1[grow * HH + k];
        if (k < II) sm->Wih0[k * HH + lr] = Wih0[grow * II + k];
    }
    for (int lr = tid; lr < HH; lr += NT) {
        int g = lr & 3, jj = lr >> 2;
        int grow = g * HH + q * 32 + jj;
        sm->b0[lr] = bih0[grow] + bhh0[grow];
        sm->b1[lr] = bih1[grow] + bhh1[grow];
        sm->wlin[lr] = Wlin[lr];
    }
    if (tid == 0) sm->blin = blin[0];
    for (int i = tid; i < 2 * HH * BC; i += NT) {
        ((float*)sm->h0buf)[i] = 0.0f;
        ((float*)sm->h1buf)[i] = 0.0f;
    }
    const int bq = tid >> 4, kq = tid & 15;   // x staging map (tid<128)
    if (tid < II * BC)
        sm->xs[0][kq * BC + bq] = x[((size_t)(bbase + bq) * TT) * II + kq];
    __syncthreads();
    cl.sync();

    float c0[2] = {0.f, 0.f}, c1[2] = {0.f, 0.f};
    const int lroff = ((warp & 3) * 8 + (lane & 7)) * 4;
    const int ks = (warp >> 2) * 4 + (lane >> 3);

    ull acc0[4][4];
#pragma unroll
    for (int g = 0; g < 4; g++)
#pragma unroll
        for (int p = 0; p < 4; p++) acc0[g][p] = 0ull;
    accum2<II / 8>(acc0, sm->Wih0, sm->xs[0], ks, lroff);   // Whh0*h0(-1)=0 skipped

    for (int t = 0; t < TT; t++) {
        const int par = t & 1, nxt = par ^ 1;

        // preload x(t+1) early (latency hides under reduce)
        float xreg = 0.f;
        if (tid < II * BC) {
            int tn = (t + 1 < TT) ? t + 1 : TT - 1;
            xreg = __ldg(&x[((size_t)(bbase + bq) * TT + tn) * II + kq]);
        }

        // (a) layer-0 reduce -> h0(t) into h0buf[par] (DSMEM replicated)
        rus(acc0, sm, sm->b0, c0, sm->h0buf, par, q, warp, lane, cl);
        if (tid < II * BC) sm->xs[nxt][kq * BC + bq] = xreg;
        CLUSTER_ARRIVE();                        // phase 1: propagate h0(t)

        // (c) hidden under barrier 1: acc1 = Whh1 * h1(t-1)
        ull acc1[4][4];
#pragma unroll
        for (int g = 0; g < 4; g++)
#pragma unroll
            for (int p = 0; p < 4; p++) acc1[g][p] = 0ull;
        accum2<HH / 8>(acc1, sm->Whh1, sm->h1buf[nxt], ks, lroff);
        CLUSTER_WAIT();                          // h0(t) visible cluster-wide

        // (e) acc1 += Wih1 * h0(t)
        accum2<HH / 8>(acc1, sm->Wih1, sm->h0buf[par], ks, lroff);

        // (f) layer-1 reduce -> h1(t) into h1buf[par]
        rus(acc1, sm, sm->b1, c1, sm->h1buf, par, q, warp, lane, cl);
        CLUSTER_ARRIVE();                        // phase 2: propagate h1(t)

        // (h) hidden under barrier 2: full layer-0 GEMM for t+1
#pragma unroll
        for (int g = 0; g < 4; g++)
#pragma unroll
            for (int p = 0; p < 4; p++) acc0[g][p] = 0ull;
        accum2<II / 8>(acc0, sm->Wih0, sm->xs[nxt], ks, lroff);
        accum2<HH / 8>(acc0, sm->Whh0, sm->h0buf[par], ks, lroff);
        CLUSTER_WAIT();                          // h1(t) visible cluster-wide

        // (j) fused ReLU + linear head: warp b handles batch b
        {
            float p = 0.f;
#pragma unroll
            for (int j = 0; j < 4; j++) {
                int k = lane + 32 * j;
                float h = sm->h1buf[par][k * BC + warp];
                p = fmaf(fmaxf(h, 0.f), sm->wlin[k], p);
            }
#pragma unroll
            for (int m = 16; m; m >>= 1)
                p += __shfl_xor_sync(0xffffffffu, p, m);
            if (lane == 0)
                out[(size_t)(bbase + warp) * TT + t] = p + sm->blin;
        }
    }
    cl.sync();
}

extern "C" void kernel_launch(void* const* d_in, const int* in_sizes, int n_in,
                              void* d_out, int out_size) {
    const float* x    = (const float*)d_in[0];
    const float* Wih0 = (const float*)d_in[1];
    const float* Whh0 = (const float*)d_in[2];
    const float* bih0 = (const float*)d_in[3];
    const float* bhh0 = (const float*)d_in[4];
    const float* Wih1 = (const float*)d_in[5];
    const float* Whh1 = (const float*)d_in[6];
    const float* bih1 = (const float*)d_in[7];
    const float* bhh1 = (const float*)d_in[8];
    const float* Wlin = (const float*)d_in[9];
    const float* blin = (const float*)d_in[10];
    float* out = (float*)d_out;

    size_t smem = sizeof(Smem);
    cudaFuncSetAttribute(lstm_kernel, cudaFuncAttributeMaxDynamicSharedMemorySize,
                         (int)smem);
    lstm_kernel<<<NCTAS, NT, smem>>>(x, Wih0, Whh0, bih0, bhh0,
                                     Wih1, Whh1, bih1, bhh1,
                                     Wlin, blin, out);
}